// round 6
// baseline (speedup 1.0000x reference)
#include <cuda_runtime.h>

#define BMAX 16384

__device__ float g_y2[BMAX * 400];    // conv2+pool output, flattened (C,H,W)
__device__ float g_w1T[400 * 128];    // fc_w transposed  [k][c]
__device__ float g_w2T[128 * 64];     // fc2_w transposed [k][c]

__device__ __forceinline__ float4 fma4(float4 a, float4 b, float4 c) {
    return make_float4(fmaf(a.x, b.x, c.x), fmaf(a.y, b.y, c.y),
                       fmaf(a.z, b.z, c.z), fmaf(a.w, b.w, c.w));
}

// ---------------------------------------------------------------------------
// Transpose kernel for FC weights (coalesced loads in k3).
// ---------------------------------------------------------------------------
__global__ void __launch_bounds__(256) kT(const float* __restrict__ fc_w,
                                          const float* __restrict__ fc2_w) {
    const int i = blockIdx.x * 256 + threadIdx.x;
    if (i < 51200) { const int r = i / 400, k = i - r * 400; g_w1T[k * 128 + r] = fc_w[i]; }
    if (i < 8192)  { const int r = i / 128, k = i - r * 128; g_w2T[k * 64 + r]  = fc2_w[i]; }
}

// ---------------------------------------------------------------------------
// Fused conv kernel, 4 images / 320 threads, dynamic smem (64.1 KB).
//   A : conv1(1->8)+bias+relu+pool  -> sy1 (stride-16 rows)
//   B1: 1D Winograd F(2,3) input transform of sy1 rows -> T (shared over oc)
//   B2: conv2 in m-space (4 FMA per 2 outputs) + pool + bias + relu -> g_y2
// Shared pool layout (floats):
//   Tbuf  [4][1920]           @ 0        (aliases sx [4][784])
//   sy1   [4][8 ic][13 y][16] @ 7680
//   suw4  [16 oc][25] float4  @ 14336    (1600 floats)
//   sw1   [72]                @ 15936
//   sb1   [8]                 @ 16008
//   sb2   [16]                @ 16016
// ---------------------------------------------------------------------------
#define K12_SMEM_FLOATS 16032

__global__ void __launch_bounds__(320) k12_conv(const float* __restrict__ x,
                                                const float* __restrict__ w1,
                                                const float* __restrict__ b1,
                                                const float* __restrict__ w2,
                                                const float* __restrict__ b2) {
    extern __shared__ __align__(16) float SM[];
    float*  Tbuf = SM;
    float*  sx   = SM;                       // alias (disjoint lifetime)
    float*  sy1  = SM + 7680;
    float4* suw4 = (float4*)(SM + 14336);
    float*  sw1  = SM + 15936;
    float*  sb1  = SM + 16008;
    float*  sb2  = SM + 16016;

    const int img0 = blockIdx.x * 4;
    const int t = threadIdx.x;

    // ---- stage 0: weights / biases / input ----
    if (t < 72) sw1[t] = w1[t];
    if (t >= 80 && t < 88)   sb1[t - 80] = b1[t - 80];
    if (t >= 88 && t < 104)  sb2[t - 88] = b2[t - 88];
    for (int i = t; i < 384; i += 320) {         // Winograd weight transform
        const int oc = i / 24, rem = i - oc * 24;
        const int ic = rem / 3, ky = rem - ic * 3;
        const float* g = w2 + oc * 72 + ic * 9 + ky * 3;
        const float a = g[0], bq = g[1], c = g[2];
        suw4[oc * 25 + ic * 3 + ky] =
            make_float4(a, 0.5f * (a + bq + c), 0.5f * (a - bq + c), c);
    }
    {
        const float4* xs = (const float4*)(x + img0 * 784);
        for (int i = t; i < 784; i += 320) ((float4*)sx)[i] = xs[i];
    }
    __syncthreads();

    // ---- phase A: conv1 + bias + relu + pool -> sy1 ----
    for (int i = t; i < 676; i += 320) {
        const int sub = i / 169;
        const int local = i - sub * 169;
        const int py = local / 13, px = local - py * 13;
        const float* xim = sx + sub * 784 + (2 * py) * 28 + 2 * px;

        float win[4][4];
#pragma unroll
        for (int j = 0; j < 4; j++) {
            const float2* rr = (const float2*)(xim + j * 28);
            const float2 a = rr[0], b = rr[1];
            win[j][0] = a.x; win[j][1] = a.y; win[j][2] = b.x; win[j][3] = b.y;
        }

        float* outp = sy1 + sub * 1664 + py * 16 + px;
#pragma unroll
        for (int oc = 0; oc < 8; oc++) {
            float c00 = 0.f, c01 = 0.f, c10 = 0.f, c11 = 0.f;
#pragma unroll
            for (int ky = 0; ky < 3; ky++)
#pragma unroll
                for (int kx = 0; kx < 3; kx++) {
                    const float wv = sw1[oc * 9 + ky * 3 + kx];
                    c00 = fmaf(win[ky][kx],         wv, c00);
                    c01 = fmaf(win[ky][kx + 1],     wv, c01);
                    c10 = fmaf(win[ky + 1][kx],     wv, c10);
                    c11 = fmaf(win[ky + 1][kx + 1], wv, c11);
                }
            const float m = fmaxf(fmaxf(c00, c01), fmaxf(c10, c11)) + sb1[oc];
            outp[oc * 208] = fmaxf(m, 0.f);
        }
    }
    __syncthreads();

    // ---- phase B1: input transform (rows 0..11, shared across 16 oc) ----
    for (int i = t; i < 384; i += 320) {
        const int img = i / 96, rem = i - img * 96;
        const int y = rem / 8, ic = rem - y * 8;
        const float4* rp = (const float4*)(sy1 + img * 1664 + ic * 208 + y * 16);
        float r[12];
#pragma unroll
        for (int m = 0; m < 3; m++) {
            const float4 v = rp[m];
            r[4 * m] = v.x; r[4 * m + 1] = v.y; r[4 * m + 2] = v.z; r[4 * m + 3] = v.w;
        }
        float4* dst = (float4*)(Tbuf + img * 1920 + (y * 8 + ic) * 20);
#pragma unroll
        for (int p = 0; p < 5; p++)
            dst[p] = make_float4(r[2 * p] - r[2 * p + 2],
                                 r[2 * p + 1] + r[2 * p + 2],
                                 r[2 * p + 2] - r[2 * p + 1],
                                 r[2 * p + 1] - r[2 * p + 3]);
    }
    __syncthreads();

    // ---- phase B2: m-space conv2 + pool + bias + relu ----
    const int sub = t / 80;
    const int r = t - sub * 80;
    const int py = r >> 4, oc = r & 15;
    const float* Timg = Tbuf + sub * 1920;
    const float4* wbase = suw4 + oc * 25;

    float4 macc[2][5];
#pragma unroll
    for (int a = 0; a < 2; a++)
#pragma unroll
        for (int p = 0; p < 5; p++) macc[a][p] = make_float4(0.f, 0.f, 0.f, 0.f);

#pragma unroll 2
    for (int ic = 0; ic < 8; ic++) {
        const float4 u0 = wbase[ic * 3 + 0];
        const float4 u1 = wbase[ic * 3 + 1];
        const float4 u2 = wbase[ic * 3 + 2];
#pragma unroll
        for (int s = 0; s < 4; s++) {
            const float4* Trow = (const float4*)(Timg + ((2 * py + s) * 8 + ic) * 20);
            float4 tr[5];
#pragma unroll
            for (int p = 0; p < 5; p++) tr[p] = Trow[p];
            if (s < 3) {   // a = 0, ky = s
                const float4 u = (s == 0) ? u0 : (s == 1) ? u1 : u2;
#pragma unroll
                for (int p = 0; p < 5; p++) macc[0][p] = fma4(tr[p], u, macc[0][p]);
            }
            if (s >= 1) {  // a = 1, ky = s-1
                const float4 u = (s == 1) ? u0 : (s == 2) ? u1 : u2;
#pragma unroll
                for (int p = 0; p < 5; p++) macc[1][p] = fma4(tr[p], u, macc[1][p]);
            }
        }
    }

    float* outp = g_y2 + (img0 + sub) * 400 + oc * 25 + py * 5;
    const float bb = sb2[oc];
#pragma unroll
    for (int p = 0; p < 5; p++) {
        const float o00 = macc[0][p].x + macc[0][p].y + macc[0][p].z;
        const float o01 = macc[0][p].y - macc[0][p].z - macc[0][p].w;
        const float o10 = macc[1][p].x + macc[1][p].y + macc[1][p].z;
        const float o11 = macc[1][p].y - macc[1][p].z - macc[1][p].w;
        const float m = fmaxf(fmaxf(o00, o01), fmaxf(o10, o11));
        outp[p] = fmaxf(m + bb, 0.f);
    }
}

// ---------------------------------------------------------------------------
// Kernel 3: fc1(400->128)+relu, fc2(128->64), fc3(64->10), 16 rows per block.
// ---------------------------------------------------------------------------
__global__ void __launch_bounds__(128) k3_fc(const float* __restrict__ fc_b,
                                             const float* __restrict__ fc2_b,
                                             const float* __restrict__ fc3_w,
                                             const float* __restrict__ fc3_b,
                                             float* __restrict__ out) {
    __shared__ __align__(16) float sx[16 * 400];
    __shared__ __align__(16) float sh1[16 * 128];
    __shared__ __align__(16) float sh2[16 * 64];
    __shared__ __align__(16) float sw3[640];
    __shared__ float sb3[10];

    const int r0 = blockIdx.x * 16;
    const int t = threadIdx.x;

    {
        const float4* xin = (const float4*)(g_y2 + r0 * 400);
        for (int i = t; i < 1600; i += 128) ((float4*)sx)[i] = xin[i];
        for (int i = t; i < 160; i += 128) ((float4*)sw3)[i] = ((const float4*)fc3_w)[i];
        if (t < 10) sb3[t] = fc3_b[t];
    }
    __syncthreads();

    {
        float acc[16];
#pragma unroll
        for (int r = 0; r < 16; r++) acc[r] = 0.f;
        const float* wp = g_w1T + t;
#pragma unroll 2
        for (int k4 = 0; k4 < 100; k4++) {
            const float w0 = wp[(4 * k4 + 0) * 128];
            const float w1 = wp[(4 * k4 + 1) * 128];
            const float w2 = wp[(4 * k4 + 2) * 128];
            const float w3 = wp[(4 * k4 + 3) * 128];
#pragma unroll
            for (int r = 0; r < 16; r++) {
                const float4 x4 = ((const float4*)sx)[r * 100 + k4];
                acc[r] = fmaf(x4.x, w0, acc[r]);
                acc[r] = fmaf(x4.y, w1, acc[r]);
                acc[r] = fmaf(x4.z, w2, acc[r]);
                acc[r] = fmaf(x4.w, w3, acc[r]);
            }
        }
        const float bb = fc_b[t];
#pragma unroll
        for (int r = 0; r < 16; r++)
            sh1[r * 128 + t] = fmaxf(acc[r] + bb, 0.f);
    }
    __syncthreads();

    {
        const int c = t & 63;
        const int rbase = (t >> 6) * 8;
        float acc[8];
#pragma unroll
        for (int r = 0; r < 8; r++) acc[r] = 0.f;
        const float* wp = g_w2T + c;
#pragma unroll 4
        for (int k4 = 0; k4 < 32; k4++) {
            const float w0 = wp[(4 * k4 + 0) * 64];
            const float w1 = wp[(4 * k4 + 1) * 64];
            const float w2 = wp[(4 * k4 + 2) * 64];
            const float w3 = wp[(4 * k4 + 3) * 64];
#pragma unroll
            for (int r = 0; r < 8; r++) {
                const float4 h4 = ((const float4*)sh1)[(rbase + r) * 32 + k4];
                acc[r] = fmaf(h4.x, w0, acc[r]);
                acc[r] = fmaf(h4.y, w1, acc[r]);
                acc[r] = fmaf(h4.z, w2, acc[r]);
                acc[r] = fmaf(h4.w, w3, acc[r]);
            }
        }
        const float bb = fc2_b[c];
#pragma unroll
        for (int r = 0; r < 8; r++)
            sh2[(rbase + r) * 64 + c] = acc[r] + bb;
    }
    __syncthreads();

    for (int idx = t; idx < 160; idx += 128) {
        const int r = idx / 10, c = idx - r * 10;
        float a = sb3[c];
        const float* h = sh2 + r * 64;
        const float* wv = sw3 + c * 64;
#pragma unroll
        for (int k = 0; k < 64; k++) a = fmaf(h[k], wv[k], a);
        out[(r0 + r) * 10 + c] = a;
    }
}

// ---------------------------------------------------------------------------
extern "C" void kernel_launch(void* const* d_in, const int* in_sizes, int n_in,
                              void* d_out, int out_size) {
    const float* x       = (const float*)d_in[0];
    const float* conv1_w = (const float*)d_in[1];
    const float* conv1_b = (const float*)d_in[2];
    const float* conv2_w = (const float*)d_in[3];
    const float* conv2_b = (const float*)d_in[4];
    const float* fc_w    = (const float*)d_in[5];
    const float* fc_b    = (const float*)d_in[6];
    const float* fc2_w   = (const float*)d_in[7];
    const float* fc2_b   = (const float*)d_in[8];
    const float* fc3_w   = (const float*)d_in[9];
    const float* fc3_b   = (const float*)d_in[10];
    float* out = (float*)d_out;

    const int B = in_sizes[0] / 784;
    const int smem_bytes = K12_SMEM_FLOATS * 4;

    static bool attr_set = false;
    if (!attr_set) {
        cudaFuncSetAttribute(k12_conv, cudaFuncAttributeMaxDynamicSharedMemorySize,
                             smem_bytes);
        attr_set = true;
    }

    kT<<<200, 256>>>(fc_w, fc2_w);
    k12_conv<<<B / 4, 320, smem_bytes>>>(x, conv1_w, conv1_b, conv2_w, conv2_b);
    k3_fc<<<B / 16, 128>>>(fc_b, fc2_b, fc3_w, fc3_b, out);
}

// round 7
// speedup vs baseline: 1.1091x; 1.1091x over previous
#include <cuda_runtime.h>

#define BMAX 16384

__device__ float g_y2[BMAX * 400];    // conv2+pool output, flattened (C,H,W)
__device__ float g_w1T[400 * 128];    // fc_w packed  [k/4][c][4]
__device__ float g_w2T[128 * 64];     // fc2_w packed [k/4][c][4]

__device__ __forceinline__ float4 fma4(float4 a, float4 b, float4 c) {
    return make_float4(fmaf(a.x, b.x, c.x), fmaf(a.y, b.y, c.y),
                       fmaf(a.z, b.z, c.z), fmaf(a.w, b.w, c.w));
}

// ---------------------------------------------------------------------------
// Weight repack: w1T[(k/4)][c][4] so k3 loads 4 k-weights per LDG.128.
// ---------------------------------------------------------------------------
__global__ void __launch_bounds__(256) kT(const float* __restrict__ fc_w,
                                          const float* __restrict__ fc2_w) {
    const int i = blockIdx.x * 256 + threadIdx.x;
    if (i < 51200) {
        const int c = i / 400, k = i - c * 400;
        g_w1T[(k >> 2) * 512 + c * 4 + (k & 3)] = fc_w[i];
    }
    if (i < 8192) {
        const int c = i / 128, k = i - c * 128;
        g_w2T[(k >> 2) * 256 + c * 4 + (k & 3)] = fc2_w[i];
    }
}

// ---------------------------------------------------------------------------
// Fused conv kernel, 2 images / 160 threads (R5 configuration — best measured).
//   A : conv1(1->8)+bias+relu+pool  -> sy1 (stride-16 rows)
//   B1: 1D Winograd F(2,3) input transform of sy1 rows -> T (shared over oc)
//   B2: conv2 in m-space (4 FMA per 2 outputs) + pool + bias + relu -> g_y2
// ---------------------------------------------------------------------------
__global__ void __launch_bounds__(160) k12_conv(const float* __restrict__ x,
                                                const float* __restrict__ w1,
                                                const float* __restrict__ b1,
                                                const float* __restrict__ w2,
                                                const float* __restrict__ b2) {
    __shared__ __align__(16) float SM[8864];
    float*  Tbuf = SM;                   // [2 img][12 y][8 ic][5 p][4] = 3840
    float*  sx   = SM;                   // [2 img][784] (alias, disjoint lifetime)
    float*  sy1  = SM + 3840;            // [2 img][8 ic][13 y][16] = 3328
    float4* suw4 = (float4*)(SM + 7168); // [16 oc][25] float4
    float*  sw1  = SM + 8768;
    float*  sb1  = SM + 8840;
    float*  sb2  = SM + 8848;

    const int img0 = blockIdx.x * 2;
    const int t = threadIdx.x;

    // ---- stage 0 ----
    if (t < 72) sw1[t] = w1[t];
    if (t >= 80 && t < 88)   sb1[t - 80] = b1[t - 80];
    if (t >= 88 && t < 104)  sb2[t - 88] = b2[t - 88];
    for (int i = t; i < 384; i += 160) {         // Winograd weight transform
        const int oc = i / 24, rem = i - oc * 24;
        const int ic = rem / 3, ky = rem - ic * 3;
        const float* g = w2 + oc * 72 + ic * 9 + ky * 3;
        const float a = g[0], bq = g[1], c = g[2];
        suw4[oc * 25 + ic * 3 + ky] =
            make_float4(a, 0.5f * (a + bq + c), 0.5f * (a - bq + c), c);
    }
    {
        const float4* xs = (const float4*)(x + img0 * 784);
        for (int i = t; i < 392; i += 160) ((float4*)sx)[i] = xs[i];
    }
    __syncthreads();

    // ---- phase A: conv1 + bias + relu + pool -> sy1 ----
    for (int i = t; i < 338; i += 160) {
        const int sub = i / 169;
        const int local = i - sub * 169;
        const int py = local / 13, px = local - py * 13;
        const float* xim = sx + sub * 784 + (2 * py) * 28 + 2 * px;

        float win[4][4];
#pragma unroll
        for (int j = 0; j < 4; j++) {
            const float2* rr = (const float2*)(xim + j * 28);
            const float2 a = rr[0], b = rr[1];
            win[j][0] = a.x; win[j][1] = a.y; win[j][2] = b.x; win[j][3] = b.y;
        }

        float* outp = sy1 + sub * 1664 + py * 16 + px;
#pragma unroll
        for (int oc = 0; oc < 8; oc++) {
            float c00 = 0.f, c01 = 0.f, c10 = 0.f, c11 = 0.f;
#pragma unroll
            for (int ky = 0; ky < 3; ky++)
#pragma unroll
                for (int kx = 0; kx < 3; kx++) {
                    const float wv = sw1[oc * 9 + ky * 3 + kx];
                    c00 = fmaf(win[ky][kx],         wv, c00);
                    c01 = fmaf(win[ky][kx + 1],     wv, c01);
                    c10 = fmaf(win[ky + 1][kx],     wv, c10);
                    c11 = fmaf(win[ky + 1][kx + 1], wv, c11);
                }
            const float m = fmaxf(fmaxf(c00, c01), fmaxf(c10, c11)) + sb1[oc];
            outp[oc * 208] = fmaxf(m, 0.f);
        }
    }
    __syncthreads();

    // ---- phase B1: input transform (rows 0..11, shared across 16 oc) ----
    for (int i = t; i < 192; i += 160) {
        const int img = i / 96, rem = i - img * 96;
        const int y = rem / 8, ic = rem - y * 8;
        const float4* rp = (const float4*)(sy1 + img * 1664 + ic * 208 + y * 16);
        float r[12];
#pragma unroll
        for (int m = 0; m < 3; m++) {
            const float4 v = rp[m];
            r[4 * m] = v.x; r[4 * m + 1] = v.y; r[4 * m + 2] = v.z; r[4 * m + 3] = v.w;
        }
        float4* dst = (float4*)(Tbuf + img * 1920 + (y * 8 + ic) * 20);
#pragma unroll
        for (int p = 0; p < 5; p++)
            dst[p] = make_float4(r[2 * p] - r[2 * p + 2],
                                 r[2 * p + 1] + r[2 * p + 2],
                                 r[2 * p + 2] - r[2 * p + 1],
                                 r[2 * p + 1] - r[2 * p + 3]);
    }
    __syncthreads();

    // ---- phase B2: m-space conv2 + pool + bias + relu ----
    const int sub = t / 80;
    const int r = t - sub * 80;
    const int py = r >> 4, oc = r & 15;
    const float* Timg = Tbuf + sub * 1920;
    const float4* wbase = suw4 + oc * 25;

    float4 macc[2][5];
#pragma unroll
    for (int a = 0; a < 2; a++)
#pragma unroll
        for (int p = 0; p < 5; p++) macc[a][p] = make_float4(0.f, 0.f, 0.f, 0.f);

#pragma unroll 2
    for (int ic = 0; ic < 8; ic++) {
        const float4 u0 = wbase[ic * 3 + 0];
        const float4 u1 = wbase[ic * 3 + 1];
        const float4 u2 = wbase[ic * 3 + 2];
#pragma unroll
        for (int s = 0; s < 4; s++) {
            const float4* Trow = (const float4*)(Timg + ((2 * py + s) * 8 + ic) * 20);
            float4 tr[5];
#pragma unroll
            for (int p = 0; p < 5; p++) tr[p] = Trow[p];
            if (s < 3) {
                const float4 u = (s == 0) ? u0 : (s == 1) ? u1 : u2;
#pragma unroll
                for (int p = 0; p < 5; p++) macc[0][p] = fma4(tr[p], u, macc[0][p]);
            }
            if (s >= 1) {
                const float4 u = (s == 1) ? u0 : (s == 2) ? u1 : u2;
#pragma unroll
                for (int p = 0; p < 5; p++) macc[1][p] = fma4(tr[p], u, macc[1][p]);
            }
        }
    }

    float* outp = g_y2 + (img0 + sub) * 400 + oc * 25 + py * 5;
    const float bb = sb2[oc];
#pragma unroll
    for (int p = 0; p < 5; p++) {
        const float o00 = macc[0][p].x + macc[0][p].y + macc[0][p].z;
        const float o01 = macc[0][p].y - macc[0][p].z - macc[0][p].w;
        const float o10 = macc[1][p].x + macc[1][p].y + macc[1][p].z;
        const float o11 = macc[1][p].y - macc[1][p].z - macc[1][p].w;
        const float m = fmaxf(fmaxf(o00, o01), fmaxf(o10, o11));
        outp[p] = fmaxf(m + bb, 0.f);
    }
}

// ---------------------------------------------------------------------------
// Kernel 3: fc1(400->128)+relu, fc2(128->64), fc3(64->10), 16 rows per block.
// Weights now packed so each thread issues LDG.128 per 4 k-values.
// ---------------------------------------------------------------------------
__global__ void __launch_bounds__(128) k3_fc(const float* __restrict__ fc_b,
                                             const float* __restrict__ fc2_b,
                                             const float* __restrict__ fc3_w,
                                             const float* __restrict__ fc3_b,
                                             float* __restrict__ out) {
    __shared__ __align__(16) float sx[16 * 400];
    __shared__ __align__(16) float sh1[16 * 128];
    __shared__ __align__(16) float sh2[16 * 64];
    __shared__ __align__(16) float sw3[640];
    __shared__ float sb3[10];

    const int r0 = blockIdx.x * 16;
    const int t = threadIdx.x;

    {
        const float4* xin = (const float4*)(g_y2 + r0 * 400);
        for (int i = t; i < 1600; i += 128) ((float4*)sx)[i] = xin[i];
        for (int i = t; i < 160; i += 128) ((float4*)sw3)[i] = ((const float4*)fc3_w)[i];
        if (t < 10) sb3[t] = fc3_b[t];
    }
    __syncthreads();

    // ---- stage 1: h1[r][t] = relu(X[r] . W1[:,t] + fc_b[t]) ----
    {
        float acc[16];
#pragma unroll
        for (int r = 0; r < 16; r++) acc[r] = 0.f;
        const float4* wp = (const float4*)g_w1T + t;   // [k4][128] float4
#pragma unroll 2
        for (int k4 = 0; k4 < 100; k4++) {
            const float4 w4 = wp[k4 * 128];
#pragma unroll
            for (int r = 0; r < 16; r++) {
                const float4 x4 = ((const float4*)sx)[r * 100 + k4];
                acc[r] = fmaf(x4.x, w4.x, acc[r]);
                acc[r] = fmaf(x4.y, w4.y, acc[r]);
                acc[r] = fmaf(x4.z, w4.z, acc[r]);
                acc[r] = fmaf(x4.w, w4.w, acc[r]);
            }
        }
        const float bb = fc_b[t];
#pragma unroll
        for (int r = 0; r < 16; r++)
            sh1[r * 128 + t] = fmaxf(acc[r] + bb, 0.f);
    }
    __syncthreads();

    // ---- stage 2: h2[r][c] = h1[r] . W2[:,c] + fc2_b[c] ----
    {
        const int c = t & 63;
        const int rbase = (t >> 6) * 8;
        float acc[8];
#pragma unroll
        for (int r = 0; r < 8; r++) acc[r] = 0.f;
        const float4* wp = (const float4*)g_w2T + c;   // [k4][64] float4
#pragma unroll 4
        for (int k4 = 0; k4 < 32; k4++) {
            const float4 w4 = wp[k4 * 64];
#pragma unroll
            for (int r = 0; r < 8; r++) {
                const float4 h4 = ((const float4*)sh1)[(rbase + r) * 32 + k4];
                acc[r] = fmaf(h4.x, w4.x, acc[r]);
                acc[r] = fmaf(h4.y, w4.y, acc[r]);
                acc[r] = fmaf(h4.z, w4.z, acc[r]);
                acc[r] = fmaf(h4.w, w4.w, acc[r]);
            }
        }
        const float bb = fc2_b[c];
#pragma unroll
        for (int r = 0; r < 8; r++)
            sh2[(rbase + r) * 64 + c] = acc[r] + bb;
    }
    __syncthreads();

    // ---- stage 3 ----
    for (int idx = t; idx < 160; idx += 128) {
        const int r = idx / 10, c = idx - r * 10;
        float a = sb3[c];
        const float* h = sh2 + r * 64;
        const float* wv = sw3 + c * 64;
#pragma unroll
        for (int k = 0; k < 64; k++) a = fmaf(h[k], wv[k], a);
        out[(r0 + r) * 10 + c] = a;
    }
}

// ---------------------------------------------------------------------------
extern "C" void kernel_launch(void* const* d_in, const int* in_sizes, int n_in,
                              void* d_out, int out_size) {
    const float* x       = (const float*)d_in[0];
    const float* conv1_w = (const float*)d_in[1];
    const float* conv1_b = (const float*)d_in[2];
    const float* conv2_w = (const float*)d_in[3];
    const float* conv2_b = (const float*)d_in[4];
    const float* fc_w    = (const float*)d_in[5];
    const float* fc_b    = (const float*)d_in[6];
    const float* fc2_w   = (const float*)d_in[7];
    const float* fc2_b   = (const float*)d_in[8];
    const float* fc3_w   = (const float*)d_in[9];
    const float* fc3_b   = (const float*)d_in[10];
    float* out = (float*)d_out;

    const int B = in_sizes[0] / 784;

    kT<<<200, 256>>>(fc_w, fc2_w);
    k12_conv<<<B / 2, 160>>>(x, conv1_w, conv1_b, conv2_w, conv2_b);
    k3_fc<<<B / 16, 128>>>(fc_b, fc2_b, fc3_w, fc3_b, out);
}